// round 11
// baseline (speedup 1.0000x reference)
#include <cuda_runtime.h>
#include <cuda_fp16.h>
#include <cstdint>
#include <cstddef>

// ---------------------------------------------------------------------------
// ActorUpAction v5: fp16 mma.sync, 512 threads, 64x32 warp tiles; big action
// layers run as one 16-quarter (256col x 32K) double-buffered cp.async weight
// pipeline, h2 stays in registers.
//   action: tanh([x,m]) -> 256x256 relu -> 256x256 relu -> dot(256) -> tanh
//   msg:    l2n(x@fc1[64x128]) -> tanh([hx,m]) -> tanh(fc2[64x192]) -> l2n(fc3[32x64])
// Output: msg_up [B,32] fp32 then action [B] fp32.
// ---------------------------------------------------------------------------

#define SA 264   // halves stride, 256-wide activation tiles (K=256+8)
#define SX 136   // halves stride, raw-x / fc1 weights (K=128+8)
#define SZ 200   // halves stride, Z / fc2 weights (K=192+8)
#define SZ2 72   // halves stride, Z2 / fc3 weights (K=64+8)
#define SWQ 40   // halves stride, weight quarter buffer (32+8)

// smem byte offsets
#define OFF_A    0         // tanh([x,m]) 128 x SA fp16 (67584 B)
#define OFF_H    67584     // raw-x (SX) / Z (SZ) / h1 (SA)  (67584 B)
#define OFF_W    135168    // msg-weight overlay region (69632 B)
#define OFF_PART 208896    // 1024 floats
#define SMEM_BYTES 212992

// overlays inside W region
#define OFF_F1   OFF_W                 // 64 x SX x2  = 17408
#define OFF_F2   (OFF_W + 20480)       // 64 x SZ x2  = 25600 -> ends 46080
#define OFF_F3   (OFF_W + 46080)       // 32 x SZ2 x2 = 4608  -> ends 50688
#define OFF_Z2   OFF_W                 // 128 x SZ2 x2 = 18432 (f1 dead)
#define OFF_QB   (OFF_W + 20480)       // quarter buf B (20480 B, f2 region, f2 dead)
#define OFF_QA   (OFF_W + 50688)       // quarter buf A (20480 B, tail) -> ends 206336

// big-layer weights in global: quarter-major fp16: [q][n][k] = q*8192 + n*32 + k
__device__ __half g_w1[65536];
__device__ __half g_w2[65536];
__device__ __half g_f1[64*128];
__device__ __half g_f2[64*192];
__device__ __half g_f3[32*64];

__global__ void cvtw_kernel(const float* __restrict__ w1, const float* __restrict__ w2,
                            const float* __restrict__ f1, const float* __restrict__ f2,
                            const float* __restrict__ f3) {
    int i = blockIdx.x * blockDim.x + threadIdx.x;   // 65536
    int n = i >> 8, K = i & 255;
    int dst = (K >> 5) * 8192 + n * 32 + (K & 31);
    g_w1[dst] = __float2half_rn(w1[i]);
    g_w2[dst] = __float2half_rn(w2[i]);
    if (i < 8192)  g_f1[i] = __float2half_rn(f1[i]);
    if (i < 12288) g_f2[i] = __float2half_rn(f2[i]);
    if (i < 2048)  g_f3[i] = __float2half_rn(f3[i]);
}

static __device__ __forceinline__ unsigned su(const void* p) {
    return (unsigned)__cvta_generic_to_shared(p);
}
static __device__ __forceinline__ void ldm_x4(uint32_t* r, unsigned a) {
    asm volatile("ldmatrix.sync.aligned.m8n8.x4.shared.b16 {%0,%1,%2,%3}, [%4];"
                 : "=r"(r[0]), "=r"(r[1]), "=r"(r[2]), "=r"(r[3]) : "r"(a));
}
static __device__ __forceinline__ void ldm_x2(uint32_t* r, unsigned a) {
    asm volatile("ldmatrix.sync.aligned.m8n8.x2.shared.b16 {%0,%1}, [%2];"
                 : "=r"(r[0]), "=r"(r[1]) : "r"(a));
}
static __device__ __forceinline__ void mma16816(float* c, const uint32_t* a, const uint32_t* b) {
    asm volatile("mma.sync.aligned.m16n8k16.row.col.f32.f16.f16.f32 "
                 "{%0,%1,%2,%3}, {%4,%5,%6,%7}, {%8,%9}, {%0,%1,%2,%3};"
                 : "+f"(c[0]), "+f"(c[1]), "+f"(c[2]), "+f"(c[3])
                 : "r"(a[0]), "r"(a[1]), "r"(a[2]), "r"(a[3]), "r"(b[0]), "r"(b[1]));
}
static __device__ __forceinline__ float ft(float v) {
    v = fminf(8.0f, fmaxf(-8.0f, v));
    float e;
    asm("ex2.approx.f32 %0, %1;" : "=f"(e) : "f"(v * 2.8853900817779268f));
    return __fdividef(e - 1.0f, e + 1.0f);
}
static __device__ __forceinline__ void cpa16(uint32_t dst, const void* src) {
    asm volatile("cp.async.cg.shared.global [%0], [%1], 16;" :: "r"(dst), "l"(src) : "memory");
}
#define CPA_COMMIT() asm volatile("cp.async.commit_group;" ::: "memory")
#define CPA_WAIT0()  asm volatile("cp.async.wait_group 0;" ::: "memory")
#define CPA_WAIT1()  asm volatile("cp.async.wait_group 1;" ::: "memory")

// Msg-branch warp GEMM: 32 rows x NF*8 cols, fp32 accum.
template <int NF, int K, int LDA, int LDW>
static __device__ __forceinline__ void warp_gemm(const __half* Aw, const __half* Ww,
                                                 float acc[2][NF][4], int lane) {
    unsigned aB = su(Aw + (lane & 15) * LDA + (lane >> 4) * 8);
#pragma unroll
    for (int k0 = 0; k0 < K; k0 += 16) {
        uint32_t a0[4], a1[4];
        ldm_x4(a0, aB + 2 * k0);
        ldm_x4(a1, aB + 32 * LDA + 2 * k0);
        if constexpr ((NF & 1) == 0) {
            unsigned bB = su(Ww + ((lane & 7) + ((lane & 16) >> 1)) * LDW +
                             ((lane >> 3) & 1) * 8);
#pragma unroll
            for (int ni = 0; ni < NF; ni += 2) {
                uint32_t b[4];
                ldm_x4(b, bB + ni * 16 * LDW + 2 * k0);
                mma16816(acc[0][ni], a0, b);
                mma16816(acc[1][ni], a1, b);
                mma16816(acc[0][ni + 1], a0, b + 2);
                mma16816(acc[1][ni + 1], a1, b + 2);
            }
        } else {
            unsigned bB = su(Ww + (lane & 7) * LDW + ((lane >> 3) & 1) * 8);
#pragma unroll
            for (int ni = 0; ni < NF; ni++) {
                uint32_t b[2];
                ldm_x2(b, bB + ni * 16 * LDW + 2 * k0);
                mma16816(acc[0][ni], a0, b);
                mma16816(acc[1][ni], a1, b);
            }
        }
    }
}

// Action warp GEMM: 64 rows x 32 cols over one K=32 quarter, accumulate.
static __device__ __forceinline__ void gemmq(const __half* Aw, const __half* Wq,
                                             float acc[4][4][4], int lane) {
    unsigned aB = su(Aw + (lane & 15) * SA + (lane >> 4) * 8);
    unsigned bB = su(Wq + ((lane & 7) + ((lane & 16) >> 1)) * SWQ + ((lane >> 3) & 1) * 8);
#pragma unroll
    for (int k0 = 0; k0 < 32; k0 += 16) {
        uint32_t a[4][4];
#pragma unroll
        for (int mf = 0; mf < 4; mf++) ldm_x4(a[mf], aB + mf * 32 * SA + 2 * k0);
        uint32_t b[8];
        ldm_x4(b, bB + 2 * k0);
        ldm_x4(b + 4, bB + 32 * SWQ + 2 * k0);   // cols 16-31: 16 rows x 80B
#pragma unroll
        for (int mf = 0; mf < 4; mf++)
#pragma unroll
            for (int nf = 0; nf < 4; nf++)
                mma16816(acc[mf][nf], a[mf], b + nf * 2);
    }
}

// cp.async one 16KB weight quarter ([256 cols][32 K]) into qoff ([256][SWQ])
static __device__ __forceinline__ void loadQ(char* smem, int qoff, const __half* gsrc,
                                             int tid) {
#pragma unroll
    for (int it = 0; it < 2; it++) {
        int i = tid + it * 512;
        int n = i >> 2, c = i & 3;
        cpa16(su(smem + qoff + n * (SWQ * 2) + c * 16), gsrc + n * 32 + c * 8);
    }
}

#define ZERO_ACC2(A)                                                \
    _Pragma("unroll") for (int _a = 0; _a < 2; _a++)                \
    _Pragma("unroll") for (int _b = 0; _b < 2; _b++)                \
    _Pragma("unroll") for (int _c = 0; _c < 4; _c++) A[_a][_b][_c] = 0.f;

__global__ void __launch_bounds__(512, 1)
actor_kernel(const float* __restrict__ gx, const float* __restrict__ gm,
             const float* __restrict__ fc1_b, const float* __restrict__ fc2_b,
             const float* __restrict__ fc3_b, const float* __restrict__ ab_b1,
             const float* __restrict__ ab_b2, const float* __restrict__ ab_w3,
             const float* __restrict__ ab_b3, float* __restrict__ out, int nrows) {
    extern __shared__ char smem[];
    __half* bufA = (__half*)(smem + OFF_A);
    __half* bufH = (__half*)(smem + OFF_H);
    float* part = (float*)(smem + OFF_PART);

    const int tid = threadIdx.x;
    const int lane = tid & 31;
    const int wid = tid >> 5;
    const int wm = wid & 3;        // msg: 4 row-tiles of 32
    const int wn = wid >> 2;       // msg: 4 col-tiles
    const int wm2 = wid & 1;       // action: 2 row-tiles of 64
    const int wn2 = wid >> 1;      // action: 8 col-tiles of 32
    const int rin = lane >> 2;
    const int cin = (lane & 3) * 2;
    const int row0 = blockIdx.x * 128;

    // ---- msg fc weights + W1 quarter-0 via cp.async ----
    {
        const __half* f1 = g_f1;
#pragma unroll
        for (int it = 0; it < 2; it++) {
            int i = tid + it * 512;
            int r = i >> 4, c = i & 15;
            cpa16(su(smem + OFF_F1 + r * (SX * 2) + c * 16), f1 + r * 128 + c * 8);
        }
        const __half* f2 = g_f2;
#pragma unroll
        for (int it = 0; it < 3; it++) {
            int i = tid + it * 512;
            int r = i / 24, c = i % 24;
            cpa16(su(smem + OFF_F2 + r * (SZ * 2) + c * 16), f2 + r * 192 + c * 8);
        }
        if (tid < 256) {
            int r = tid >> 3, c = tid & 7;
            cpa16(su(smem + OFF_F3 + r * (SZ2 * 2) + c * 16), g_f3 + r * 64 + c * 8);
        }
        loadQ(smem, OFF_QA, g_w1, tid);   // W1 quarter 0 prefetch
        CPA_COMMIT();
    }

    // ---- stage inputs: raw x fp16 -> bufH (SX); tanh(x),tanh(m) -> bufA (SA) ----
    const float4* x4 = (const float4*)(gx + (size_t)row0 * 128);
    const float4* m4 = (const float4*)(gm + (size_t)row0 * 128);
#pragma unroll
    for (int it = 0; it < 8; it++) {
        int i = tid + it * 512;
        int r = i >> 5, c = i & 31;
        float4 v = x4[i];
        __half2* xd = (__half2*)(bufH + r * SX + c * 4);
        xd[0] = __floats2half2_rn(v.x, v.y);
        xd[1] = __floats2half2_rn(v.z, v.w);
        __half2* ad = (__half2*)(bufA + r * SA + c * 4);
        ad[0] = __floats2half2_rn(ft(v.x), ft(v.y));
        ad[1] = __floats2half2_rn(ft(v.z), ft(v.w));
        float4 w = m4[i];
        __half2* md = (__half2*)(bufA + r * SA + 128 + c * 4);
        md[0] = __floats2half2_rn(ft(w.x), ft(w.y));
        md[1] = __floats2half2_rn(ft(w.z), ft(w.w));
    }
    CPA_WAIT0();
    __syncthreads();

    // ================= message branch =================
    {   // fc1: [128,64] = rawx @ f1^T, l2norm
        float acc[2][2][4];
        ZERO_ACC2(acc)
        warp_gemm<2, 128, SX, SX>(bufH + wm * 32 * SX,
                                  (__half*)(smem + OFF_F1) + wn * 16 * SX, acc, lane);
        float ssq[4] = {0.f, 0.f, 0.f, 0.f};
#pragma unroll
        for (int ni = 0; ni < 2; ni++) {
            int col = wn * 16 + ni * 8 + cin;
            float b0 = fc1_b[col], b1 = fc1_b[col + 1];
#pragma unroll
            for (int mi = 0; mi < 2; mi++) {
                acc[mi][ni][0] += b0; acc[mi][ni][1] += b1;
                acc[mi][ni][2] += b0; acc[mi][ni][3] += b1;
                ssq[mi * 2]     += acc[mi][ni][0] * acc[mi][ni][0] + acc[mi][ni][1] * acc[mi][ni][1];
                ssq[mi * 2 + 1] += acc[mi][ni][2] * acc[mi][ni][2] + acc[mi][ni][3] * acc[mi][ni][3];
            }
        }
#pragma unroll
        for (int j = 0; j < 4; j++) {
            ssq[j] += __shfl_xor_sync(0xffffffffu, ssq[j], 1);
            ssq[j] += __shfl_xor_sync(0xffffffffu, ssq[j], 2);
        }
        if ((lane & 3) == 0) {
#pragma unroll
            for (int j = 0; j < 4; j++)
                part[wn * 128 + wm * 32 + j * 8 + rin] = ssq[j];
        }
        __syncthreads();   // fc1 reads of rawx done; part ready
        float inv[4];
#pragma unroll
        for (int j = 0; j < 4; j++) {
            int row = wm * 32 + j * 8 + rin;
            float t = part[row] + part[128 + row] + part[256 + row] + part[384 + row];
            inv[j] = 1.0f / fmaxf(sqrtf(t), 1e-12f);
        }
#pragma unroll
        for (int mi = 0; mi < 2; mi++)
#pragma unroll
            for (int ni = 0; ni < 2; ni++) {
                int row = wm * 32 + mi * 16 + rin;
                int col = wn * 16 + ni * 8 + cin;
                *(__half2*)(bufH + row * SZ + col) = __floats2half2_rn(
                    ft(acc[mi][ni][0] * inv[mi * 2]), ft(acc[mi][ni][1] * inv[mi * 2]));
                *(__half2*)(bufH + (row + 8) * SZ + col) = __floats2half2_rn(
                    ft(acc[mi][ni][2] * inv[mi * 2 + 1]), ft(acc[mi][ni][3] * inv[mi * 2 + 1]));
            }
    }
    // copy tanh(m) -> Z[:,64:192]
#pragma unroll
    for (int it = 0; it < 8; it++) {
        int i = tid + it * 512;
        int r = i >> 5, c = i & 31;
        *(uint2*)(bufH + r * SZ + 64 + c * 4) = *(const uint2*)(bufA + r * SA + 128 + c * 4);
    }
    __syncthreads();

    {   // fc2: tanh(Z @ f2^T) -> Z2
        float acc[2][2][4];
        ZERO_ACC2(acc)
        warp_gemm<2, 192, SZ, SZ>(bufH + wm * 32 * SZ,
                                  (__half*)(smem + OFF_F2) + wn * 16 * SZ, acc, lane);
        __syncthreads();   // all fc2 reads done; f2 region dead
        loadQ(smem, OFF_QB, g_w1 + 8192, tid);   // W1 quarter 1 -> QB (f2 region)
        CPA_COMMIT();
#pragma unroll
        for (int mi = 0; mi < 2; mi++)
#pragma unroll
            for (int ni = 0; ni < 2; ni++) {
                int row = wm * 32 + mi * 16 + rin;
                int col = wn * 16 + ni * 8 + cin;
                float b0 = fc2_b[col], b1 = fc2_b[col + 1];
                *(__half2*)((__half*)(smem + OFF_Z2) + row * SZ2 + col) =
                    __floats2half2_rn(ft(acc[mi][ni][0] + b0), ft(acc[mi][ni][1] + b1));
                *(__half2*)((__half*)(smem + OFF_Z2) + (row + 8) * SZ2 + col) =
                    __floats2half2_rn(ft(acc[mi][ni][2] + b0), ft(acc[mi][ni][3] + b1));
            }
    }
    __syncthreads();

    {   // fc3: [128,32] = Z2 @ f3^T, l2norm -> msg out
        float acc[2][1][4];
#pragma unroll
        for (int _a = 0; _a < 2; _a++)
#pragma unroll
            for (int _c = 0; _c < 4; _c++) acc[_a][0][_c] = 0.f;
        warp_gemm<1, 64, SZ2, SZ2>((__half*)(smem + OFF_Z2) + wm * 32 * SZ2,
                                   (__half*)(smem + OFF_F3) + wn * 8 * SZ2, acc, lane);
        int col = wn * 8 + cin;
        float b0 = fc3_b[col], b1 = fc3_b[col + 1];
        float ssq[4];
#pragma unroll
        for (int mi = 0; mi < 2; mi++) {
            acc[mi][0][0] += b0; acc[mi][0][1] += b1;
            acc[mi][0][2] += b0; acc[mi][0][3] += b1;
            ssq[mi * 2]     = acc[mi][0][0] * acc[mi][0][0] + acc[mi][0][1] * acc[mi][0][1];
            ssq[mi * 2 + 1] = acc[mi][0][2] * acc[mi][0][2] + acc[mi][0][3] * acc[mi][0][3];
        }
#pragma unroll
        for (int j = 0; j < 4; j++) {
            ssq[j] += __shfl_xor_sync(0xffffffffu, ssq[j], 1);
            ssq[j] += __shfl_xor_sync(0xffffffffu, ssq[j], 2);
        }
        if ((lane & 3) == 0) {
#pragma unroll
            for (int j = 0; j < 4; j++)
                part[wn * 128 + wm * 32 + j * 8 + rin] = ssq[j];
        }
        __syncthreads();
#pragma unroll
        for (int mi = 0; mi < 2; mi++)
#pragma unroll
            for (int s = 0; s < 2; s++) {
                int row = wm * 32 + mi * 16 + s * 8 + rin;
                float t = part[row] + part[128 + row] + part[256 + row] + part[384 + row];
                float inv = 1.0f / fmaxf(sqrtf(t), 1e-12f);
                float* od = out + (size_t)(row0 + row) * 32 + col;
                od[0] = acc[mi][0][s * 2] * inv;
                od[1] = acc[mi][0][s * 2 + 1] * inv;
            }
    }
    __syncthreads();   // msg done

    // ================= action branch: 16-quarter pipeline =================
    // invariant at iter q: quarter q resident+visible; load of q+1 issued.
    float acc[4][4][4];
#pragma unroll
    for (int a = 0; a < 4; a++)
#pragma unroll
        for (int b = 0; b < 4; b++)
#pragma unroll
            for (int c = 0; c < 4; c++) acc[a][b][c] = 0.f;

    const __half* Qb0 = (const __half*)(smem + OFF_QA) + wn2 * 32 * SWQ;
    const __half* Qb1 = (const __half*)(smem + OFF_QB) + wn2 * 32 * SWQ;

#pragma unroll 1
    for (int q = 0; q < 16; q++) {
        const __half* Ap = ((q < 8) ? bufA : bufH) + wm2 * 64 * SA + (q & 7) * 32;
        gemmq(Ap, (q & 1) ? Qb1 : Qb0, acc, lane);
        __syncthreads();                          // reads of buf[q&1] complete
        if (q + 2 < 16) {
            loadQ(smem, (q & 1) ? OFF_QB : OFF_QA,
                  (q + 2 < 8) ? (g_w1 + (q + 2) * 8192) : (g_w2 + (q - 6) * 8192), tid);
            CPA_COMMIT();
        }
        if (q == 7) {   // layer-1 epilogue: h1 = relu(acc + b1) -> bufH; reset acc
#pragma unroll
            for (int mf = 0; mf < 4; mf++)
#pragma unroll
                for (int nf = 0; nf < 4; nf++) {
                    int row = wm2 * 64 + mf * 16 + rin;
                    int col = wn2 * 32 + nf * 8 + cin;
                    float b0 = ab_b1[col], b1v = ab_b1[col + 1];
                    *(__half2*)(bufH + row * SA + col) = __floats2half2_rn(
                        fmaxf(acc[mf][nf][0] + b0, 0.f), fmaxf(acc[mf][nf][1] + b1v, 0.f));
                    *(__half2*)(bufH + (row + 8) * SA + col) = __floats2half2_rn(
                        fmaxf(acc[mf][nf][2] + b0, 0.f), fmaxf(acc[mf][nf][3] + b1v, 0.f));
                    acc[mf][nf][0] = acc[mf][nf][1] = 0.f;
                    acc[mf][nf][2] = acc[mf][nf][3] = 0.f;
                }
        }
        if (q + 1 < 16) {
            if (q + 2 < 16) { CPA_WAIT1(); } else { CPA_WAIT0(); }
            __syncthreads();                      // q+1 visible (and h1 at q==7)
        }
    }

    // ---- final: action = tanh( relu(acc + b2) . w3 + b3 ), from registers ----
    {
        float s[8];
#pragma unroll
        for (int j = 0; j < 8; j++) s[j] = 0.f;
#pragma unroll
        for (int nf = 0; nf < 4; nf++) {
            int col = wn2 * 32 + nf * 8 + cin;
            float b20 = ab_b2[col], b21 = ab_b2[col + 1];
            float w30 = ab_w3[col], w31 = ab_w3[col + 1];
#pragma unroll
            for (int mf = 0; mf < 4; mf++) {
                s[mf * 2]     += fmaxf(acc[mf][nf][0] + b20, 0.f) * w30 +
                                 fmaxf(acc[mf][nf][1] + b21, 0.f) * w31;
                s[mf * 2 + 1] += fmaxf(acc[mf][nf][2] + b20, 0.f) * w30 +
                                 fmaxf(acc[mf][nf][3] + b21, 0.f) * w31;
            }
        }
#pragma unroll
        for (int j = 0; j < 8; j++) {
            s[j] += __shfl_xor_sync(0xffffffffu, s[j], 1);
            s[j] += __shfl_xor_sync(0xffffffffu, s[j], 2);
        }
        __syncthreads();   // part free
        if ((lane & 3) == 0) {
#pragma unroll
            for (int mf = 0; mf < 4; mf++)
#pragma unroll
                for (int rh = 0; rh < 2; rh++)
                    part[wn2 * 128 + wm2 * 64 + mf * 16 + rh * 8 + rin] = s[mf * 2 + rh];
        }
    }
    __syncthreads();
    if (tid < 128) {
        float s = 0.f;
#pragma unroll
        for (int q = 0; q < 8; q++) s += part[q * 128 + tid];
        out[(size_t)nrows * 32 + row0 + tid] = ft(s + ab_b3[0]);
    }
}

extern "C" void kernel_launch(void* const* d_in, const int* in_sizes, int n_in,
                              void* d_out, int out_size) {
    const float* x     = (const float*)d_in[0];
    const float* m     = (const float*)d_in[1];
    const float* fc1_w = (const float*)d_in[2];
    const float* fc1_b = (const float*)d_in[3];
    const float* fc2_w = (const float*)d_in[4];
    const float* fc2_b = (const float*)d_in[5];
    const float* fc3_w = (const float*)d_in[6];
    const float* fc3_b = (const float*)d_in[7];
    const float* ab_w1 = (const float*)d_in[8];
    const float* ab_b1 = (const float*)d_in[9];
    const float* ab_w2 = (const float*)d_in[10];
    const float* ab_b2 = (const float*)d_in[11];
    const float* ab_w3 = (const float*)d_in[12];
    const float* ab_b3 = (const float*)d_in[13];
    float* out = (float*)d_out;
    int nrows = in_sizes[0] / 128;

    static bool attr_done = false;
    if (!attr_done) {
        cudaFuncSetAttribute(actor_kernel,
                             cudaFuncAttributeMaxDynamicSharedMemorySize, SMEM_BYTES);
        attr_done = true;
    }

    cvtw_kernel<<<256, 256>>>(ab_w1, ab_w2, fc1_w, fc2_w, fc3_w);
    actor_kernel<<<nrows / 128, 512, SMEM_BYTES>>>(
        x, m, fc1_b, fc2_b, fc3_b, ab_b1, ab_b2, ab_w3, ab_b3, out, nrows);
}

// round 13
// speedup vs baseline: 1.0654x; 1.0654x over previous
#include <cuda_runtime.h>
#include <cuda_fp16.h>
#include <cstdint>
#include <cstddef>

// ---------------------------------------------------------------------------
// ActorUpAction v6b: fp16 mma.sync, 256 threads/CTA, 2 CTAs/SM (64-row tiles).
// Cross-CTA overlap hides blocking weight loads. 64x32 action warp tiles,
// 16 weight quarters (256col x 32K each; 8 per layer), h2 in regs.
// (v6 + fix: full 16-quarter contraction; v6 only did K=128 per layer)
//   action: tanh([x,m]) -> 256x256 relu -> 256x256 relu -> dot(256) -> tanh
//   msg:    l2n(x@fc1[64x128]) -> tanh([hx,m]) -> tanh(fc2[64x192]) -> l2n(fc3[32x64])
// Output: msg_up [B,32] fp32 then action [B] fp32.
// ---------------------------------------------------------------------------

#define SA 264   // halves stride, 256-wide activation tiles (K=256+8)
#define SX 136   // halves stride, raw-x / fc1 weights (K=128+8)
#define SZ 200   // halves stride, Z / fc2 weights (K=192+8)
#define SZ2 72   // halves stride, Z2 / fc3 weights (K=64+8)
#define SWQ 40   // halves stride, weight quarter buffer (32+8)

// smem byte offsets (per 64-row CTA)
#define OFF_A    0         // tanh(xm) 64 x SA fp16 = 33792
#define OFF_H    33792     // raw-x (SX,17408) / Z (SZ,25600) / h1 (SA,33792)
#define OFF_F3   (OFF_H + 25600)   // 32 x SZ2 x2 = 4608 (H-tail; dead before h1)
#define OFF_W    67584     // 25600: F2 during msg; quarter buf (20480) in action
#define OFF_F1   93184     // 17408: F1; then Z2 (64 x SZ2 x2 = 9216)
#define OFF_Z2   OFF_F1
#define OFF_PART 110592    // 512 floats = 2048
#define SMEM_BYTES 112640

// big-layer weights in global: quarter-major fp16: [q][n][k] = q*8192 + n*32 + k
__device__ __half g_w1[65536];
__device__ __half g_w2[65536];
__device__ __half g_f1[64*128];
__device__ __half g_f2[64*192];
__device__ __half g_f3[32*64];

__global__ void cvtw_kernel(const float* __restrict__ w1, const float* __restrict__ w2,
                            const float* __restrict__ f1, const float* __restrict__ f2,
                            const float* __restrict__ f3) {
    int i = blockIdx.x * blockDim.x + threadIdx.x;   // 65536
    int n = i >> 8, K = i & 255;
    int dst = (K >> 5) * 8192 + n * 32 + (K & 31);
    g_w1[dst] = __float2half_rn(w1[i]);
    g_w2[dst] = __float2half_rn(w2[i]);
    if (i < 8192)  g_f1[i] = __float2half_rn(f1[i]);
    if (i < 12288) g_f2[i] = __float2half_rn(f2[i]);
    if (i < 2048)  g_f3[i] = __float2half_rn(f3[i]);
}

static __device__ __forceinline__ unsigned su(const void* p) {
    return (unsigned)__cvta_generic_to_shared(p);
}
static __device__ __forceinline__ void ldm_x4(uint32_t* r, unsigned a) {
    asm volatile("ldmatrix.sync.aligned.m8n8.x4.shared.b16 {%0,%1,%2,%3}, [%4];"
                 : "=r"(r[0]), "=r"(r[1]), "=r"(r[2]), "=r"(r[3]) : "r"(a));
}
static __device__ __forceinline__ void ldm_x2(uint32_t* r, unsigned a) {
    asm volatile("ldmatrix.sync.aligned.m8n8.x2.shared.b16 {%0,%1}, [%2];"
                 : "=r"(r[0]), "=r"(r[1]) : "r"(a));
}
static __device__ __forceinline__ void mma16816(float* c, const uint32_t* a, const uint32_t* b) {
    asm volatile("mma.sync.aligned.m16n8k16.row.col.f32.f16.f16.f32 "
                 "{%0,%1,%2,%3}, {%4,%5,%6,%7}, {%8,%9}, {%0,%1,%2,%3};"
                 : "+f"(c[0]), "+f"(c[1]), "+f"(c[2]), "+f"(c[3])
                 : "r"(a[0]), "r"(a[1]), "r"(a[2]), "r"(a[3]), "r"(b[0]), "r"(b[1]));
}
static __device__ __forceinline__ float ft(float v) {
    v = fminf(8.0f, fmaxf(-8.0f, v));
    float e;
    asm("ex2.approx.f32 %0, %1;" : "=f"(e) : "f"(v * 2.8853900817779268f));
    return __fdividef(e - 1.0f, e + 1.0f);
}
static __device__ __forceinline__ void cpa16(uint32_t dst, const void* src) {
    asm volatile("cp.async.cg.shared.global [%0], [%1], 16;" :: "r"(dst), "l"(src) : "memory");
}
#define CPA_COMMIT() asm volatile("cp.async.commit_group;" ::: "memory")
#define CPA_WAIT0()  asm volatile("cp.async.wait_group 0;" ::: "memory")

// Msg-branch warp GEMM: 32 rows x NF*8 cols, fp32 accum.
template <int NF, int K, int LDA, int LDW>
static __device__ __forceinline__ void warp_gemm(const __half* Aw, const __half* Ww,
                                                 float acc[2][NF][4], int lane) {
    unsigned aB = su(Aw + (lane & 15) * LDA + (lane >> 4) * 8);
#pragma unroll
    for (int k0 = 0; k0 < K; k0 += 16) {
        uint32_t a0[4], a1[4];
        ldm_x4(a0, aB + 2 * k0);
        ldm_x4(a1, aB + 32 * LDA + 2 * k0);
        if constexpr ((NF & 1) == 0) {
            unsigned bB = su(Ww + ((lane & 7) + ((lane & 16) >> 1)) * LDW +
                             ((lane >> 3) & 1) * 8);
#pragma unroll
            for (int ni = 0; ni < NF; ni += 2) {
                uint32_t b[4];
                ldm_x4(b, bB + ni * 16 * LDW + 2 * k0);
                mma16816(acc[0][ni], a0, b);
                mma16816(acc[1][ni], a1, b);
                mma16816(acc[0][ni + 1], a0, b + 2);
                mma16816(acc[1][ni + 1], a1, b + 2);
            }
        } else {
            unsigned bB = su(Ww + (lane & 7) * LDW + ((lane >> 3) & 1) * 8);
#pragma unroll
            for (int ni = 0; ni < NF; ni++) {
                uint32_t b[2];
                ldm_x2(b, bB + ni * 16 * LDW + 2 * k0);
                mma16816(acc[0][ni], a0, b);
                mma16816(acc[1][ni], a1, b);
            }
        }
    }
}

// Action warp GEMM: 64 rows x 32 cols over one K=32 quarter, accumulate.
static __device__ __forceinline__ void gemmq(const __half* Aw, const __half* Wq,
                                             float acc[4][4][4], int lane) {
    unsigned aB = su(Aw + (lane & 15) * SA + (lane >> 4) * 8);
    unsigned bB = su(Wq + ((lane & 7) + ((lane & 16) >> 1)) * SWQ + ((lane >> 3) & 1) * 8);
#pragma unroll
    for (int k0 = 0; k0 < 32; k0 += 16) {
        uint32_t a[4][4];
#pragma unroll
        for (int mf = 0; mf < 4; mf++) ldm_x4(a[mf], aB + mf * 32 * SA + 2 * k0);
        uint32_t b[8];
        ldm_x4(b, bB + 2 * k0);
        ldm_x4(b + 4, bB + 32 * SWQ + 2 * k0);   // cols 16-31 (16 rows x 80 B)
#pragma unroll
        for (int mf = 0; mf < 4; mf++)
#pragma unroll
            for (int nf = 0; nf < 4; nf++)
                mma16816(acc[mf][nf], a[mf], b + nf * 2);
    }
}

// cp.async one 16KB weight quarter ([256 cols][32 K]) into OFF_W
static __device__ __forceinline__ void loadQ(char* smem, const __half* gsrc, int tid) {
#pragma unroll
    for (int it = 0; it < 4; it++) {
        int i = tid + it * 256;
        int n = i >> 2, c = i & 3;
        cpa16(su(smem + OFF_W + n * (SWQ * 2) + c * 16), gsrc + n * 32 + c * 8);
    }
}

#define ZERO_ACC2(A)                                                \
    _Pragma("unroll") for (int _a = 0; _a < 2; _a++)                \
    _Pragma("unroll") for (int _b = 0; _b < 2; _b++)                \
    _Pragma("unroll") for (int _c = 0; _c < 4; _c++) A[_a][_b][_c] = 0.f;

__global__ void __launch_bounds__(256, 2)
actor_kernel(const float* __restrict__ gx, const float* __restrict__ gm,
             const float* __restrict__ fc1_b, const float* __restrict__ fc2_b,
             const float* __restrict__ fc3_b, const float* __restrict__ ab_b1,
             const float* __restrict__ ab_b2, const float* __restrict__ ab_w3,
             const float* __restrict__ ab_b3, float* __restrict__ out, int nrows) {
    extern __shared__ char smem[];
    __half* bufA = (__half*)(smem + OFF_A);
    __half* bufH = (__half*)(smem + OFF_H);
    float* part = (float*)(smem + OFF_PART);

    const int tid = threadIdx.x;
    const int lane = tid & 31;
    const int wid = tid >> 5;          // 0..7
    const int wm = wid & 1;            // msg: 2 row-tiles of 32
    const int wn = wid >> 1;           // msg: 4 col-tiles
    const int wn2 = wid;               // action: 8 col-tiles of 32
    const int rin = lane >> 2;
    const int cin = (lane & 3) * 2;
    const int row0 = blockIdx.x * 64;

    // ---- msg fc weights via cp.async ----
    {
        const __half* f1 = g_f1;
#pragma unroll
        for (int it = 0; it < 4; it++) {
            int i = tid + it * 256;
            int r = i >> 4, c = i & 15;
            cpa16(su(smem + OFF_F1 + r * (SX * 2) + c * 16), f1 + r * 128 + c * 8);
        }
        const __half* f2 = g_f2;
#pragma unroll
        for (int it = 0; it < 6; it++) {
            int i = tid + it * 256;
            int r = i / 24, c = i % 24;
            cpa16(su(smem + OFF_W + r * (SZ * 2) + c * 16), f2 + r * 192 + c * 8);
        }
        {   // fc3 [32][64]: 256 uint4
            int r = tid >> 3, c = tid & 7;
            cpa16(su(smem + OFF_F3 + r * (SZ2 * 2) + c * 16), g_f3 + r * 64 + c * 8);
        }
        CPA_COMMIT();
    }

    // ---- stage inputs: raw x fp16 -> bufH (SX); tanh(x),tanh(m) -> bufA (SA) ----
    const float4* x4 = (const float4*)(gx + (size_t)row0 * 128);
    const float4* m4 = (const float4*)(gm + (size_t)row0 * 128);
#pragma unroll
    for (int it = 0; it < 8; it++) {
        int i = tid + it * 256;
        int r = i >> 5, c = i & 31;   // 32 float4 per row, 64 rows
        float4 v = x4[i];
        __half2* xd = (__half2*)(bufH + r * SX + c * 4);
        xd[0] = __floats2half2_rn(v.x, v.y);
        xd[1] = __floats2half2_rn(v.z, v.w);
        __half2* ad = (__half2*)(bufA + r * SA + c * 4);
        ad[0] = __floats2half2_rn(ft(v.x), ft(v.y));
        ad[1] = __floats2half2_rn(ft(v.z), ft(v.w));
        float4 w = m4[i];
        __half2* md = (__half2*)(bufA + r * SA + 128 + c * 4);
        md[0] = __floats2half2_rn(ft(w.x), ft(w.y));
        md[1] = __floats2half2_rn(ft(w.z), ft(w.w));
    }
    CPA_WAIT0();
    __syncthreads();

    // ================= message branch =================
    {   // fc1: [64,64] = rawx @ f1^T, l2norm
        float acc[2][2][4];
        ZERO_ACC2(acc)
        warp_gemm<2, 128, SX, SX>(bufH + wm * 32 * SX,
                                  (__half*)(smem + OFF_F1) + wn * 16 * SX, acc, lane);
        float ssq[4] = {0.f, 0.f, 0.f, 0.f};
#pragma unroll
        for (int ni = 0; ni < 2; ni++) {
            int col = wn * 16 + ni * 8 + cin;
            float b0 = fc1_b[col], b1 = fc1_b[col + 1];
#pragma unroll
            for (int mi = 0; mi < 2; mi++) {
                acc[mi][ni][0] += b0; acc[mi][ni][1] += b1;
                acc[mi][ni][2] += b0; acc[mi][ni][3] += b1;
                ssq[mi * 2]     += acc[mi][ni][0] * acc[mi][ni][0] + acc[mi][ni][1] * acc[mi][ni][1];
                ssq[mi * 2 + 1] += acc[mi][ni][2] * acc[mi][ni][2] + acc[mi][ni][3] * acc[mi][ni][3];
            }
        }
#pragma unroll
        for (int j = 0; j < 4; j++) {
            ssq[j] += __shfl_xor_sync(0xffffffffu, ssq[j], 1);
            ssq[j] += __shfl_xor_sync(0xffffffffu, ssq[j], 2);
        }
        if ((lane & 3) == 0) {
#pragma unroll
            for (int j = 0; j < 4; j++)
                part[wn * 64 + wm * 32 + j * 8 + rin] = ssq[j];
        }
        __syncthreads();   // fc1 reads of rawx done; part ready
        float inv[4];
#pragma unroll
        for (int j = 0; j < 4; j++) {
            int row = wm * 32 + j * 8 + rin;
            float t = part[row] + part[64 + row] + part[128 + row] + part[192 + row];
            inv[j] = 1.0f / fmaxf(sqrtf(t), 1e-12f);
        }
#pragma unroll
        for (int mi = 0; mi < 2; mi++)
#pragma unroll
            for (int ni = 0; ni < 2; ni++) {
                int row = wm * 32 + mi * 16 + rin;
                int col = wn * 16 + ni * 8 + cin;
                *(__half2*)(bufH + row * SZ + col) = __floats2half2_rn(
                    ft(acc[mi][ni][0] * inv[mi * 2]), ft(acc[mi][ni][1] * inv[mi * 2]));
                *(__half2*)(bufH + (row + 8) * SZ + col) = __floats2half2_rn(
                    ft(acc[mi][ni][2] * inv[mi * 2 + 1]), ft(acc[mi][ni][3] * inv[mi * 2 + 1]));
            }
    }
    // copy tanh(m) -> Z[:,64:192]
#pragma unroll
    for (int it = 0; it < 8; it++) {
        int i = tid + it * 256;
        int r = i >> 5, c = i & 31;
        *(uint2*)(bufH + r * SZ + 64 + c * 4) = *(const uint2*)(bufA + r * SA + 128 + c * 4);
    }
    __syncthreads();

    {   // fc2: tanh(Z @ f2^T) -> Z2
        float acc[2][2][4];
        ZERO_ACC2(acc)
        warp_gemm<2, 192, SZ, SZ>(bufH + wm * 32 * SZ,
                                  (__half*)(smem + OFF_W) + wn * 16 * SZ, acc, lane);
        __syncthreads();   // all fc2 reads done; F2 region (OFF_W) dead
        loadQ(smem, g_w1, tid);   // prefetch W1 quarter 0
        CPA_COMMIT();
#pragma unroll
        for (int mi = 0; mi < 2; mi++)
#pragma unroll
            for (int ni = 0; ni < 2; ni++) {
                int row = wm * 32 + mi * 16 + rin;
                int col = wn * 16 + ni * 8 + cin;
                float b0 = fc2_b[col], b1 = fc2_b[col + 1];
                *(__half2*)((__half*)(smem + OFF_Z2) + row * SZ2 + col) =
                    __floats2half2_rn(ft(acc[mi][ni][0] + b0), ft(acc[mi][ni][1] + b1));
                *(__half2*)((__half*)(smem + OFF_Z2) + (row + 8) * SZ2 + col) =
                    __floats2half2_rn(ft(acc[mi][ni][2] + b0), ft(acc[mi][ni][3] + b1));
            }
    }
    __syncthreads();

    {   // fc3: [64,32] = Z2 @ f3^T, l2norm -> msg out
        float acc[2][1][4];
#pragma unroll
        for (int _a = 0; _a < 2; _a++)
#pragma unroll
            for (int _c = 0; _c < 4; _c++) acc[_a][0][_c] = 0.f;
        warp_gemm<1, 64, SZ2, SZ2>((__half*)(smem + OFF_Z2) + wm * 32 * SZ2,
                                   (__half*)(smem + OFF_F3) + wn * 8 * SZ2, acc, lane);
        int col = wn * 8 + cin;
        float b0 = fc3_b[col], b1 = fc3_b[col + 1];
        float ssq[4];
#pragma unroll
        for (int mi = 0; mi < 2; mi++) {
            acc[mi][0][0] += b0; acc[mi][0][1] += b1;
            acc[mi][0][2] += b0; acc[mi][0][3] += b1;
            ssq[mi * 2]     = acc[mi][0][0] * acc[mi][0][0] + acc[mi][0][1] * acc[mi][0][1];
            ssq[mi * 2 + 1] = acc[mi][0][2] * acc[mi][0][2] + acc[mi][0][3] * acc[mi][0][3];
        }
#pragma unroll
        for (int j = 0; j < 4; j++) {
            ssq[j] += __shfl_xor_sync(0xffffffffu, ssq[j], 1);
            ssq[j] += __shfl_xor_sync(0xffffffffu, ssq[j], 2);
        }
        if ((lane & 3) == 0) {
#pragma unroll
            for (int j = 0; j < 4; j++)
                part[wn * 64 + wm * 32 + j * 8 + rin] = ssq[j];
        }
        __syncthreads();
#pragma unroll
        for (int mi = 0; mi < 2; mi++)
#pragma unroll
            for (int s = 0; s < 2; s++) {
                int row = wm * 32 + mi * 16 + s * 8 + rin;
                float t = part[row] + part[64 + row] + part[128 + row] + part[192 + row];
                float inv = 1.0f / fmaxf(sqrtf(t), 1e-12f);
                float* od = out + (size_t)(row0 + row) * 32 + col;
                od[0] = acc[mi][0][s * 2] * inv;
                od[1] = acc[mi][0][s * 2 + 1] * inv;
            }
    }

    // ================= action: 16 quarters (8 per layer), blocking loads ==========
    float acc[4][4][4];
#pragma unroll
    for (int a = 0; a < 4; a++)
#pragma unroll
        for (int b = 0; b < 4; b++)
#pragma unroll
            for (int c = 0; c < 4; c++) acc[a][b][c] = 0.f;

    const __half* Qw = (const __half*)(smem + OFF_W) + wn2 * 32 * SWQ;

    CPA_WAIT0();
    __syncthreads();   // W1-q0 visible; msg reads of OFF_W long done

#pragma unroll 1
    for (int q = 0; q < 16; q++) {
        const __half* Ap = ((q < 8) ? bufA : bufH) + (q & 7) * 32;
        gemmq(Ap, Qw, acc, lane);
        if (q == 7) {   // layer-1 epilogue: h1 = relu(acc+b1) -> bufH; reset acc
#pragma unroll
            for (int mf = 0; mf < 4; mf++)
#pragma unroll
                for (int nf = 0; nf < 4; nf++) {
                    int row = mf * 16 + rin;
                    int col = wn2 * 32 + nf * 8 + cin;
                    float b0 = ab_b1[col], b1v = ab_b1[col + 1];
                    *(__half2*)(bufH + row * SA + col) = __floats2half2_rn(
                        fmaxf(acc[mf][nf][0] + b0, 0.f), fmaxf(acc[mf][nf][1] + b1v, 0.f));
                    *(__half2*)(bufH + (row + 8) * SA + col) = __floats2half2_rn(
                        fmaxf(acc[mf][nf][2] + b0, 0.f), fmaxf(acc[mf][nf][3] + b1v, 0.f));
                    acc[mf][nf][0] = acc[mf][nf][1] = 0.f;
                    acc[mf][nf][2] = acc[mf][nf][3] = 0.f;
                }
        }
        __syncthreads();   // quarter reads done (and h1 written at q==7)
        if (q < 15) {
            loadQ(smem, (q + 1 < 8) ? (g_w1 + (q + 1) * 8192) : (g_w2 + (q - 7) * 8192),
                  tid);
            CPA_COMMIT(); CPA_WAIT0();
            __syncthreads();   // next quarter visible (covers h1 visibility too)
        }
    }

    // ---- final: action = tanh( relu(acc + b2) . w3 + b3 ), from registers ----
    {
        float s[8];
#pragma unroll
        for (int j = 0; j < 8; j++) s[j] = 0.f;
#pragma unroll
        for (int nf = 0; nf < 4; nf++) {
            int col = wn2 * 32 + nf * 8 + cin;
            float b20 = ab_b2[col], b21 = ab_b2[col + 1];
            float w30 = ab_w3[col], w31 = ab_w3[col + 1];
#pragma unroll
            for (int mf = 0; mf < 4; mf++) {
                s[mf * 2]     += fmaxf(acc[mf][nf][0] + b20, 0.f) * w30 +
                                 fmaxf(acc[mf][nf][1] + b21, 0.f) * w31;
                s[mf * 2 + 1] += fmaxf(acc[mf][nf][2] + b20, 0.f) * w30 +
                                 fmaxf(acc[mf][nf][3] + b21, 0.f) * w31;
            }
        }
#pragma unroll
        for (int j = 0; j < 8; j++) {
            s[j] += __shfl_xor_sync(0xffffffffu, s[j], 1);
            s[j] += __shfl_xor_sync(0xffffffffu, s[j], 2);
        }
        __syncthreads();   // part free (msg usage done)
        if ((lane & 3) == 0) {
#pragma unroll
            for (int mf = 0; mf < 4; mf++)
#pragma unroll
                for (int rh = 0; rh < 2; rh++)
                    part[wn2 * 64 + mf * 16 + rh * 8 + rin] = s[mf * 2 + rh];
        }
    }
    __syncthreads();
    if (tid < 64) {
        float s = 0.f;
#pragma unroll
        for (int q = 0; q < 8; q++) s += part[q * 64 + tid];
        out[(size_t)nrows * 32 + row0 + tid] = ft(s + ab_b3[0]);
    }
}

extern "C" void kernel_launch(void* const* d_in, const int* in_sizes, int n_in,
                              void* d_out, int out_size) {
    const float* x     = (const float*)d_in[0];
    const float* m     = (const float*)d_in[1];
    const float* fc1_w = (const float*)d_in[2];
    const float* fc1_b = (const float*)d_in[3];
    const float* fc2_w = (const float*)d_in[4];
    const float* fc2_b = (const float*)d_in[5];
    const float* fc3_w = (const float*)d_in[6];
    const float* fc3_b = (const float*)d_in[7];
    const float* ab_w1 = (const float*)d_in[8];
    const float* ab_b1 = (const float*)d_in[9];
    const float* ab_w2 = (const float*)d_in[10];
    const float* ab_b2 = (const float*)d_in[11];
    const float* ab_w3 = (const float*)d_in[12];
    const float* ab_b3 = (const float*)d_in[13];
    float* out = (float*)d_out;
    int nrows = in_sizes[0] / 128;

    static bool attr_done = false;
    if (!attr_done) {
        cudaFuncSetAttribute(actor_kernel,
                             cudaFuncAttributeMaxDynamicSharedMemorySize, SMEM_BYTES);
        attr_done = true;
    }

    cvtw_kernel<<<256, 256>>>(ab_w1, ab_w2, fc1_w, fc2_w, fc3_w);
    actor_kernel<<<nrows / 64, 256, SMEM_BYTES>>>(
        x, m, fc1_b, fc2_b, fc3_b, ab_b1, ab_b2, ab_w3, ab_b3, out, nrows);
}

// round 16
// speedup vs baseline: 1.1267x; 1.0575x over previous
#include <cuda_runtime.h>
#include <cuda_fp16.h>
#include <cstdint>
#include <cstddef>

// ---------------------------------------------------------------------------
// ActorUpAction v7: R10 structure (512 thr, 64x32 warp tiles, h2 in regs) +
// double-buffered K=64 weight eighths (256col x 64K, 36.9KB) with cp.async
// hidden under gemms; e0/e1 prefetched during msg tail. 227KB smem headroom.
//   action: tanh([x,m]) -> 256x256 relu -> 256x256 relu -> dot(256) -> tanh
//   msg:    l2n(x@fc1[64x128]) -> tanh([hx,m]) -> tanh(fc2[64x192]) -> l2n(fc3[32x64])
// Output: msg_up [B,32] fp32 then action [B] fp32.
// ---------------------------------------------------------------------------

#define SA 264   // halves stride, 256-wide activation tiles (K=256+8)
#define SX 136   // halves stride, raw-x / fc1 weights (K=128+8)
#define SZ 200   // halves stride, Z / fc2 weights (K=192+8)
#define SZ2 72   // halves stride, Z2 / fc3 weights (K=64+8)
#define SW2 72   // halves stride, weight eighth buffer (64+8)

// smem byte offsets
#define OFF_A    0         // tanh([x,m]) 128 x SA fp16 (67584 B)
#define OFF_H    67584     // raw-x (SX) / Z (SZ) / h1 (SA)  (67584 B)
#define OFF_W    135168    // 73728 B: two 36864B eighth buffers (msg overlays below)
#define OFF_WB0  OFF_W
#define OFF_WB1  (OFF_W + 36864)
#define OFF_PART 208896    // 1024 floats (4096 B)
#define SMEM_BYTES 212992

// msg-phase overlays inside W region
#define OFF_F1   OFF_W              // 64 x SX x2  = 17408, dead after fc1
#define OFF_F2   (OFF_W + 17408)    // 64 x SZ x2  = 25600 -> ends 43008, dead after fc2
#define OFF_F3   (OFF_W + 43008)    // 32 x SZ2 x2 = 4608  -> ends 47616, dead after fc3
#define OFF_Z2   (OFF_W + 47616)    // 128 x SZ2 x2 = 18432 -> ends 66048, dead after fc3

// big-layer weights in global: eighth-major fp16: [e][n][k] = e*16384 + n*64 + k
__device__ __half g_w1[65536];
__device__ __half g_w2[65536];
__device__ __half g_f1[64*128];
__device__ __half g_f2[64*192];
__device__ __half g_f3[32*64];

__global__ void cvtw_kernel(const float* __restrict__ w1, const float* __restrict__ w2,
                            const float* __restrict__ f1, const float* __restrict__ f2,
                            const float* __restrict__ f3) {
    int i = blockIdx.x * blockDim.x + threadIdx.x;   // 65536
    int n = i >> 8, K = i & 255;
    int dst = (K >> 6) * 16384 + n * 64 + (K & 63);
    g_w1[dst] = __float2half_rn(w1[i]);
    g_w2[dst] = __float2half_rn(w2[i]);
    if (i < 8192)  g_f1[i] = __float2half_rn(f1[i]);
    if (i < 12288) g_f2[i] = __float2half_rn(f2[i]);
    if (i < 2048)  g_f3[i] = __float2half_rn(f3[i]);
}

static __device__ __forceinline__ unsigned su(const void* p) {
    return (unsigned)__cvta_generic_to_shared(p);
}
static __device__ __forceinline__ void ldm_x4(uint32_t* r, unsigned a) {
    asm volatile("ldmatrix.sync.aligned.m8n8.x4.shared.b16 {%0,%1,%2,%3}, [%4];"
                 : "=r"(r[0]), "=r"(r[1]), "=r"(r[2]), "=r"(r[3]) : "r"(a));
}
static __device__ __forceinline__ void ldm_x2(uint32_t* r, unsigned a) {
    asm volatile("ldmatrix.sync.aligned.m8n8.x2.shared.b16 {%0,%1}, [%2];"
                 : "=r"(r[0]), "=r"(r[1]) : "r"(a));
}
static __device__ __forceinline__ void mma16816(float* c, const uint32_t* a, const uint32_t* b) {
    asm volatile("mma.sync.aligned.m16n8k16.row.col.f32.f16.f16.f32 "
                 "{%0,%1,%2,%3}, {%4,%5,%6,%7}, {%8,%9}, {%0,%1,%2,%3};"
                 : "+f"(c[0]), "+f"(c[1]), "+f"(c[2]), "+f"(c[3])
                 : "r"(a[0]), "r"(a[1]), "r"(a[2]), "r"(a[3]), "r"(b[0]), "r"(b[1]));
}
static __device__ __forceinline__ float ft(float v) {
    v = fminf(8.0f, fmaxf(-8.0f, v));
    float e;
    asm("ex2.approx.f32 %0, %1;" : "=f"(e) : "f"(v * 2.8853900817779268f));
    return __fdividef(e - 1.0f, e + 1.0f);
}
static __device__ __forceinline__ void cpa16(uint32_t dst, const void* src) {
    asm volatile("cp.async.cg.shared.global [%0], [%1], 16;" :: "r"(dst), "l"(src) : "memory");
}
#define CPA_COMMIT() asm volatile("cp.async.commit_group;" ::: "memory")
#define CPA_WAIT0()  asm volatile("cp.async.wait_group 0;" ::: "memory")
#define CPA_WAIT1()  asm volatile("cp.async.wait_group 1;" ::: "memory")

// Msg-branch warp GEMM: 32 rows x NF*8 cols, fp32 accum.
template <int NF, int K, int LDA, int LDW>
static __device__ __forceinline__ void warp_gemm(const __half* Aw, const __half* Ww,
                                                 float acc[2][NF][4], int lane) {
    unsigned aB = su(Aw + (lane & 15) * LDA + (lane >> 4) * 8);
#pragma unroll
    for (int k0 = 0; k0 < K; k0 += 16) {
        uint32_t a0[4], a1[4];
        ldm_x4(a0, aB + 2 * k0);
        ldm_x4(a1, aB + 32 * LDA + 2 * k0);
        if constexpr ((NF & 1) == 0) {
            unsigned bB = su(Ww + ((lane & 7) + ((lane & 16) >> 1)) * LDW +
                             ((lane >> 3) & 1) * 8);
#pragma unroll
            for (int ni = 0; ni < NF; ni += 2) {
                uint32_t b[4];
                ldm_x4(b, bB + ni * 16 * LDW + 2 * k0);
                mma16816(acc[0][ni], a0, b);
                mma16816(acc[1][ni], a1, b);
                mma16816(acc[0][ni + 1], a0, b + 2);
                mma16816(acc[1][ni + 1], a1, b + 2);
            }
        } else {
            unsigned bB = su(Ww + (lane & 7) * LDW + ((lane >> 3) & 1) * 8);
#pragma unroll
            for (int ni = 0; ni < NF; ni++) {
                uint32_t b[2];
                ldm_x2(b, bB + ni * 16 * LDW + 2 * k0);
                mma16816(acc[0][ni], a0, b);
                mma16816(acc[1][ni], a1, b);
            }
        }
    }
}

// Action warp GEMM: 64 rows x 32 cols over one K=64 eighth, accumulate.
// A pre-offset to the eighth's 64-col window (stride SA). W: [32 cols][SW2].
static __device__ __forceinline__ void gemmE(const __half* Aw, const __half* Wq,
                                             float acc[4][4][4], int lane) {
    unsigned aB = su(Aw + (lane & 15) * SA + (lane >> 4) * 8);
    unsigned bB = su(Wq + ((lane & 7) + ((lane & 16) >> 1)) * SW2 + ((lane >> 3) & 1) * 8);
#pragma unroll
    for (int k0 = 0; k0 < 64; k0 += 16) {
        uint32_t a[4][4];
#pragma unroll
        for (int mf = 0; mf < 4; mf++) ldm_x4(a[mf], aB + mf * 32 * SA + 2 * k0);
        uint32_t b[8];
        ldm_x4(b, bB + 2 * k0);
        ldm_x4(b + 4, bB + 32 * SW2 + 2 * k0);   // cols 16-31: 16 rows = 32*SW2 bytes
#pragma unroll
        for (int mf = 0; mf < 4; mf++)
#pragma unroll
            for (int nf = 0; nf < 4; nf++)
                mma16816(acc[mf][nf], a[mf], b + nf * 2);
    }
}

// cp.async one 36864B weight eighth ([256 cols][64 K]) into buffer at qoff
static __device__ __forceinline__ void loadE(char* smem, int qoff, const __half* gsrc,
                                             int tid) {
#pragma unroll
    for (int it = 0; it < 4; it++) {
        int i = tid + it * 512;
        int n = i >> 3, c = i & 7;   // 8 uint4 per 64-half row
        cpa16(su(smem + qoff + n * (SW2 * 2) + c * 16), gsrc + n * 64 + c * 8);
    }
}

#define ZERO_ACC2(A)                                                \
    _Pragma("unroll") for (int _a = 0; _a < 2; _a++)                \
    _Pragma("unroll") for (int _b = 0; _b < 2; _b++)                \
    _Pragma("unroll") for (int _c = 0; _c < 4; _c++) A[_a][_b][_c] = 0.f;

__global__ void __launch_bounds__(512, 1)
actor_kernel(const float* __restrict__ gx, const float* __restrict__ gm,
             const float* __restrict__ fc1_b, const float* __restrict__ fc2_b,
             const float* __restrict__ fc3_b, const float* __restrict__ ab_b1,
             const float* __restrict__ ab_b2, const float* __restrict__ ab_w3,
             const float* __restrict__ ab_b3, float* __restrict__ out, int nrows) {
    extern __shared__ char smem[];
    __half* bufA = (__half*)(smem + OFF_A);
    __half* bufH = (__half*)(smem + OFF_H);
    float* part = (float*)(smem + OFF_PART);

    const int tid = threadIdx.x;
    const int lane = tid & 31;
    const int wid = tid >> 5;
    const int wm = wid & 3;        // msg: 4 row-tiles of 32
    const int wn = wid >> 2;       // msg: 4 col-tiles
    const int wm2 = wid & 1;       // action: 2 row-tiles of 64
    const int wn2 = wid >> 1;      // action: 8 col-tiles of 32
    const int rin = lane >> 2;
    const int cin = (lane & 3) * 2;
    const int row0 = blockIdx.x * 128;

    // ---- msg fc weights via cp.async ----
    {
        const __half* f1 = g_f1;
#pragma unroll
        for (int it = 0; it < 2; it++) {
            int i = tid + it * 512;
            int r = i >> 4, c = i & 15;
            cpa16(su(smem + OFF_F1 + r * (SX * 2) + c * 16), f1 + r * 128 + c * 8);
        }
        const __half* f2 = g_f2;
#pragma unroll
        for (int it = 0; it < 3; it++) {
            int i = tid + it * 512;
            int r = i / 24, c = i % 24;
            cpa16(su(smem + OFF_F2 + r * (SZ * 2) + c * 16), f2 + r * 192 + c * 8);
        }
        if (tid < 256) {
            int r = tid >> 3, c = tid & 7;
            cpa16(su(smem + OFF_F3 + r * (SZ2 * 2) + c * 16), g_f3 + r * 64 + c * 8);
        }
        CPA_COMMIT();
    }

    // ---- stage inputs: raw x fp16 -> bufH (SX); tanh(x),tanh(m) -> bufA (SA) ----
    const float4* x4 = (const float4*)(gx + (size_t)row0 * 128);
    const float4* m4 = (const float4*)(gm + (size_t)row0 * 128);
#pragma unroll
    for (int it = 0; it < 8; it++) {
        int i = tid + it * 512;
        int r = i >> 5, c = i & 31;
        float4 v = x4[i];
        __half2* xd = (__half2*)(bufH + r * SX + c * 4);
        xd[0] = __floats2half2_rn(v.x, v.y);
        xd[1] = __floats2half2_rn(v.z, v.w);
        __half2* ad = (__half2*)(bufA + r * SA + c * 4);
        ad[0] = __floats2half2_rn(ft(v.x), ft(v.y));
        ad[1] = __floats2half2_rn(ft(v.z), ft(v.w));
        float4 w = m4[i];
        __half2* md = (__half2*)(bufA + r * SA + 128 + c * 4);
        md[0] = __floats2half2_rn(ft(w.x), ft(w.y));
        md[1] = __floats2half2_rn(ft(w.z), ft(w.w));
    }
    CPA_WAIT0();
    __syncthreads();

    // ================= message branch =================
    {   // fc1: [128,64] = rawx @ f1^T, l2norm
        float acc[2][2][4];
        ZERO_ACC2(acc)
        warp_gemm<2, 128, SX, SX>(bufH + wm * 32 * SX,
                                  (__half*)(smem + OFF_F1) + wn * 16 * SX, acc, lane);
        float ssq[4] = {0.f, 0.f, 0.f, 0.f};
#pragma unroll
        for (int ni = 0; ni < 2; ni++) {
            int col = wn * 16 + ni * 8 + cin;
            float b0 = fc1_b[col], b1 = fc1_b[col + 1];
#pragma unroll
            for (int mi = 0; mi < 2; mi++) {
                acc[mi][ni][0] += b0; acc[mi][ni][1] += b1;
                acc[mi][ni][2] += b0; acc[mi][ni][3] += b1;
                ssq[mi * 2]     += acc[mi][ni][0] * acc[mi][ni][0] + acc[mi][ni][1] * acc[mi][ni][1];
                ssq[mi * 2 + 1] += acc[mi][ni][2] * acc[mi][ni][2] + acc[mi][ni][3] * acc[mi][ni][3];
            }
        }
#pragma unroll
        for (int j = 0; j < 4; j++) {
            ssq[j] += __shfl_xor_sync(0xffffffffu, ssq[j], 1);
            ssq[j] += __shfl_xor_sync(0xffffffffu, ssq[j], 2);
        }
        if ((lane & 3) == 0) {
#pragma unroll
            for (int j = 0; j < 4; j++)
                part[wn * 128 + wm * 32 + j * 8 + rin] = ssq[j];
        }
        __syncthreads();   // fc1 reads of rawx + f1 done; part ready
        float inv[4];
#pragma unroll
        for (int j = 0; j < 4; j++) {
            int row = wm * 32 + j * 8 + rin;
            float t = part[row] + part[128 + row] + part[256 + row] + part[384 + row];
            inv[j] = 1.0f / fmaxf(sqrtf(t), 1e-12f);
        }
#pragma unroll
        for (int mi = 0; mi < 2; mi++)
#pragma unroll
            for (int ni = 0; ni < 2; ni++) {
                int row = wm * 32 + mi * 16 + rin;
                int col = wn * 16 + ni * 8 + cin;
                *(__half2*)(bufH + row * SZ + col) = __floats2half2_rn(
                    ft(acc[mi][ni][0] * inv[mi * 2]), ft(acc[mi][ni][1] * inv[mi * 2]));
                *(__half2*)(bufH + (row + 8) * SZ + col) = __floats2half2_rn(
                    ft(acc[mi][ni][2] * inv[mi * 2 + 1]), ft(acc[mi][ni][3] * inv[mi * 2 + 1]));
            }
    }
    // copy tanh(m) -> Z[:,64:192]
#pragma unroll
    for (int it = 0; it < 8; it++) {
        int i = tid + it * 512;
        int r = i >> 5, c = i & 31;
        *(uint2*)(bufH + r * SZ + 64 + c * 4) = *(const uint2*)(bufA + r * SA + 128 + c * 4);
    }
    __syncthreads();

    {   // fc2: tanh(Z @ f2^T) -> Z2
        float acc[2][2][4];
        ZERO_ACC2(acc)
        warp_gemm<2, 192, SZ, SZ>(bufH + wm * 32 * SZ,
                                  (__half*)(smem + OFF_F2) + wn * 16 * SZ, acc, lane);
        __syncthreads();   // all fc2 reads done; f1 + f2-head (buffer 0 region) dead
        loadE(smem, OFF_WB0, g_w1, tid);   // prefetch W1 eighth 0 under fc2-epi + fc3
        CPA_COMMIT();
#pragma unroll
        for (int mi = 0; mi < 2; mi++)
#pragma unroll
            for (int ni = 0; ni < 2; ni++) {
                int row = wm * 32 + mi * 16 + rin;
                int col = wn * 16 + ni * 8 + cin;
                float b0 = fc2_b[col], b1 = fc2_b[col + 1];
                *(__half2*)((__half*)(smem + OFF_Z2) + row * SZ2 + col) =
                    __floats2half2_rn(ft(acc[mi][ni][0] + b0), ft(acc[mi][ni][1] + b1));
                *(__half2*)((__half*)(smem + OFF_Z2) + (row + 8) * SZ2 + col) =
                    __floats2half2_rn(ft(acc[mi][ni][2] + b0), ft(acc[mi][ni][3] + b1));
            }
    }
    __syncthreads();

    {   // fc3: [128,32] = Z2 @ f3^T, l2norm -> msg out
        float acc[2][1][4];
#pragma unroll
        for (int _a = 0; _a < 2; _a++)
#pragma unroll
            for (int _c = 0; _c < 4; _c++) acc[_a][0][_c] = 0.f;
        warp_gemm<1, 64, SZ2, SZ2>((__half*)(smem + OFF_Z2) + wm * 32 * SZ2,
                                   (__half*)(smem + OFF_F3) + wn * 8 * SZ2, acc, lane);
        int col = wn * 8 + cin;
        float b0 = fc3_b[col], b1 = fc3_b[col + 1];
        float ssq[4];
#pragma unroll
        for (int mi = 0; mi < 2; mi++) {
            acc[mi][0][0] += b0; acc[mi][0][1] += b1;
            acc[mi][0][2] += b0; acc[mi][0][3] += b1;
            ssq[mi * 2]     = acc[mi][0][0] * acc[mi][0][0] + acc[mi][0][1] * acc[mi][0][1];
            ssq[mi * 2 + 1] = acc[mi][0][2] * acc[mi][0][2] + acc[mi][0][3] * acc[mi][0][3];
        }
#pragma unroll
        for (int j = 0; j < 4; j++) {
            ssq[j] += __shfl_xor_sync(0xffffffffu, ssq[j], 1);
            ssq[j] += __shfl_xor_sync(0xffffffffu, ssq[j], 2);
        }
        if ((lane & 3) == 0) {
#pragma unroll
            for (int j = 0; j < 4; j++)
                part[wn * 128 + wm * 32 + j * 8 + rin] = ssq[j];
        }
        __syncthreads();   // all fc3 gemm reads (Z2, f3 = buffer 1 region) done
        loadE(smem, OFF_WB1, g_w1 + 16384, tid);   // prefetch W1 eighth 1
        CPA_COMMIT();
#pragma unroll
        for (int mi = 0; mi < 2; mi++)
#pragma unroll
            for (int s = 0; s < 2; s++) {
                int row = wm * 32 + mi * 16 + s * 8 + rin;
                float t = part[row] + part[128 + row] + part[256 + row] + part[384 + row];
                float inv = 1.0f / fmaxf(sqrtf(t), 1e-12f);
                float* od = out + (size_t)(row0 + row) * 32 + col;
                od[0] = acc[mi][0][s * 2] * inv;
                od[1] = acc[mi][0][s * 2 + 1] * inv;
            }
    }

    // ================= action: 8-eighth double-buffered pipeline =================
    float acc[4][4][4];
#pragma unroll
    for (int a = 0; a < 4; a++)
#pragma unroll
        for (int b = 0; b < 4; b++)
#pragma unroll
            for (int c = 0; c < 4; c++) acc[a][b][c] = 0.f;

    const __half* Qw0 = (const __half*)(smem + OFF_WB0) + wn2 * 32 * SW2;
    const __half* Qw1 = (const __half*)(smem + OFF_WB1) + wn2 * 32 * SW2;

    CPA_WAIT1();       // e0 landed (e1 may still fly)
    __syncthreads();

#pragma unroll 1
    for (int i = 0; i < 8; i++) {
        const __half* Ap = ((i < 4) ? bufA : bufH) + wm2 * 64 * SA + (i & 3) * 64;
        gemmE(Ap, (i & 1) ? Qw1 : Qw0, acc, lane);
        if (i == 3) {   // layer-1 epilogue: h1 = relu(acc+b1) -> bufH; reset acc
#pragma unroll
            for (int mf = 0; mf < 4; mf++)
#pragma unroll
                for (int nf = 0; nf < 4; nf++) {
                    int row = wm2 * 64 + mf * 16 + rin;
                    int col = wn2 * 32 + nf * 8 + cin;
                    float b0 = ab_b1[col], b1v = ab_b1[col + 1];
                    *(__half2*)(bufH + row * SA + col) = __floats2half2_rn(
                        fmaxf(acc[mf][nf][0] + b0, 0.f), fmaxf(acc[mf][nf][1] + b1v, 0.f));
                    *(__half2*)(bufH + (row + 8) * SA + col) = __floats2half2_rn(
                        fmaxf(acc[mf][nf][2] + b0, 0.f), fmaxf(acc[mf][nf][3] + b1v, 0.f));
                    acc[mf][nf][0] = acc[mf][nf][1] = 0.f;
                    acc[mf][nf][2] = acc[mf][nf][3] = 0.f;
                }
        }
        if (i < 7) {
            CPA_WAIT0();       // eighth i+1 landed
            __syncthreads();   // reads of buf[i&1] done + visibility (h1 at i==3)
            if (i < 6) {
                const __half* src = (i + 2 < 4) ? (g_w1 + (i + 2) * 16384)
                                                : (g_w2 + (i - 2) * 16384);
                loadE(smem, (i & 1) ? OFF_WB1 : OFF_WB0, src, tid);
                CPA_COMMIT();
            }
        }
    }

    // ---- final: action = tanh( relu(acc + b2) . w3 + b3 ), from registers ----
    {
        float s[8];
#pragma unroll
        for (int j = 0; j < 8; j++) s[j] = 0.f;
#pragma unroll
        for (int nf = 0; nf < 4; nf++) {
            int col = wn2 * 32 + nf * 8 + cin;
            float b20 = ab_b2[col], b21 = ab_b2[col + 1];
            float w30 = ab_w3[col], w31 = ab_w3[col + 1];
#pragma unroll
            for (int mf = 0; mf < 4; mf++) {
                s[mf * 2]     += fmaxf(acc[mf][nf][0] + b20, 0.f) * w30 +
                                 fmaxf(acc[mf][nf][1] + b21, 0.f) * w31;
                s[mf * 2 + 1] += fmaxf(acc[mf][nf][2] + b20, 0.f) * w30 +
                                 fmaxf(acc[mf][nf][3] + b21, 0.f) * w31;
            }
        }
#pragma unroll
        for (int j = 0; j < 8; j++) {
            s[j] += __shfl_xor_sync(0xffffffffu, s[j], 1);
            s[j] += __shfl_xor_sync(0xffffffffu, s[j], 2);
        }
        __syncthreads();   // part free (msg usage done)
        if ((lane & 3) == 0) {
#pragma unroll
            for (int mf = 0; mf < 4; mf++)
#pragma unroll
                for (int rh = 0; rh < 2; rh++)
                    part[wn2 * 128 + wm2 * 64 + mf * 16 + rh * 8 + rin] = s[mf * 2 + rh];
        }
    }
    __syncthreads();
    if (tid < 128) {
        float s = 0.f;
#pragma unroll
        for (int q = 0; q < 8; q++) s += part[q * 128 + tid];
        out[(size_t)nrows * 32 + row0 + tid] = ft(s + ab_b3[0]);
    }
}

extern "C" void kernel_launch(void* const* d_in, const int* in_sizes, int n_in,
                              void* d_out, int out_size) {
    const float* x     = (const float*)d_in[0];
    const float* m     = (const float*)d_in[1];
    const float* fc1_w = (const float*)d_in[2];
    const float* fc1_b = (const float*)d_in[3];
    const float* fc2_w = (const float*)d_in[4];
    const float* fc2_b = (const float*)d_in[5];
    const float* fc3_w = (const float*)d_in[6];
    const float* fc3_b = (const float*)d_in[7];
    const float* ab_w1 = (const float*)d_in[8];
    const float* ab_b1 = (const float*)d_in[9];
    const float* ab_w2 = (const float*)d_in[10];
    const float* ab_b2 = (const float*)d_in[11];
    const float* ab_w3 = (const float*)d_in[12];
    const float* ab_b3 = (const float*)d_in[13];
    float* out = (float*)d_out;
    int nrows = in_sizes[0] / 128;

    static bool attr_done = false;
    if (!attr_done) {
        cudaFuncSetAttribute(actor_kernel,
                             cudaFuncAttributeMaxDynamicSharedMemorySize, SMEM_BYTES);
        attr_done = true;
    }

    cvtw_kernel<<<256, 256>>>(ab_w1, ab_w2, fc1_w, fc2_w, fc3_w);
    actor_kernel<<<nrows / 128, 512, SMEM_BYTES>>>(
        x, m, fc1_b, fc2_b, fc3_b, ab_b1, ab_b2, ab_w3, ab_b3, out, nrows);
}